// round 15
// baseline (speedup 1.0000x reference)
#include <cuda_runtime.h>
#include <cuda_bf16.h>
#include <cuda_fp16.h>
#include <cstdint>

#define NSEQ 384
#define CIN  128
#define NH   4
#define DH   32
#define NTOK (NSEQ*NSEQ)
#define LOG2E 1.4426950408889634f

// fp16 smem geometry (bytes)
#define XSB 272     // k1/k3 A rows: frag b32 loads bank-perfect
#define WSB 288     // k1/k3 W rows: LDS.64 frag loads bank-perfect
#define KHB 80      // k2 K rows (40 halves): b32 loads bank-perfect
#define VSTH 392    // k2 V^T rows (halves): b32 loads bank-perfect

// ---- helpers ----
__device__ __forceinline__ float ex2(float x) {
    float r; asm("ex2.approx.f32 %0, %1;" : "=f"(r) : "f"(x)); return r;
}
__device__ __forceinline__ void mma_f16(float c[4],
    uint32_t a0, uint32_t a1, uint32_t a2, uint32_t a3, uint32_t b0, uint32_t b1)
{
    asm("mma.sync.aligned.m16n8k16.row.col.f32.f16.f16.f32 "
        "{%0,%1,%2,%3}, {%4,%5,%6,%7}, {%8,%9}, {%0,%1,%2,%3};"
        : "+f"(c[0]), "+f"(c[1]), "+f"(c[2]), "+f"(c[3])
        : "r"(a0), "r"(a1), "r"(a2), "r"(a3), "r"(b0), "r"(b1));
}
__device__ __forceinline__ uint32_t s2u(const void* p) {
    uint32_t a;
    asm("{ .reg .u64 t; cvta.to.shared.u64 t, %1; cvt.u32.u64 %0, t; }" : "=r"(a) : "l"(p));
    return a;
}
__device__ __forceinline__ void cpa16(uint32_t dst, const void* src) {
    asm volatile("cp.async.cg.shared.global [%0], [%1], 16;" :: "r"(dst), "l"(src));
}
#define CPA_COMMIT() asm volatile("cp.async.commit_group;" ::: "memory")
#define CPA_WAIT(n)  asm volatile("cp.async.wait_group %0;" :: "n"(n) : "memory")
__device__ __forceinline__ uint32_t pkh2(float a, float b) {
    __half2 h = __floats2half2_rn(a, b);
    return *(uint32_t*)&h;
}

// ---- scratch ----
__device__ __half g_qh[NSEQ*NH*NSEQ*DH];   // fp16, q pre-scaled by sc*log2e
__device__ __half g_kh[NSEQ*NH*NSEQ*DH];   // fp16
__device__ __half g_vh[NSEQ*NH*NSEQ*DH];   // fp16
__device__ __align__(16) __half g_acth[(size_t)NTOK*CIN];  // fp16 gate -> gated attn out
__device__ float  g_eb [NH*NTOK];          // ex2(tri-bias*log2e - 6)
__device__ __align__(16) __half g_wh[5*CIN*CIN];  // fp16, k-pair permuted weights

// ============================================================================
// Kernel 0: weights -> fp16, k-pair permuted (B frag = one LDS.64)
// ============================================================================
__global__ void k0_prep(const float* __restrict__ wq, const float* __restrict__ wk,
                        const float* __restrict__ wv, const float* __restrict__ wg,
                        const float* __restrict__ wo)
{
    const int idx = blockIdx.x * 256 + threadIdx.x;      // 81920
    const int m   = idx >> 14;
    const int rem = idx & 16383;
    const int o   = rem >> 7, c = rem & 127;
    const float* srcs[5] = {wq, wk, wv, wg, wo};
    const float v = srcs[m][o*CIN + c];
    const int j    = (c >> 1) & 7;
    const int slot = 2*(j & 3) + (j >> 2);
    const int cperm = (c & ~15) | (slot << 1) | (c & 1);
    g_wh[m*16384 + o*128 + cperm] = __float2half_rn(v);
}

// ============================================================================
// Kernel 1: LayerNorm + q/k/v/gate projections (fp16 mma) + tri-bias.
// All outputs fp16.
// ============================================================================
__global__ __launch_bounds__(256, 2) void k1_ln_proj(
    const float* __restrict__ x,   const float* __restrict__ gamma,
    const float* __restrict__ beta,const float* __restrict__ wbias,
    const float* __restrict__ bg)
{
    extern __shared__ char smc[];
    char* wb[2] = { smc, smc + 64*WSB };

    const int tid  = threadIdx.x;
    const int warp = tid >> 5, lane = tid & 31;
    const int gr   = lane >> 2, gc = lane & 3;
    const int t0   = blockIdx.x * 128;

    // ---- LayerNorm -> xs (fp16) ----
    const float4 gm = *(const float4*)(gamma + lane*4);
    const float4 bt = *(const float4*)(beta  + lane*4);
    for (int kk = 0; kk < 16; kk++) {
        const int lt = warp*16 + kk;
        const float4 xv = *(const float4*)(x + (size_t)(t0+lt)*CIN + lane*4);
        float s = xv.x + xv.y + xv.z + xv.w;
        #pragma unroll
        for (int o = 16; o; o >>= 1) s += __shfl_xor_sync(0xffffffffu, s, o);
        const float mu = s * (1.0f/128.0f);
        const float d0 = xv.x-mu, d1 = xv.y-mu, d2 = xv.z-mu, d3 = xv.w-mu;
        float vs = d0*d0 + d1*d1 + d2*d2 + d3*d3;
        #pragma unroll
        for (int o = 16; o; o >>= 1) vs += __shfl_xor_sync(0xffffffffu, vs, o);
        const float rs = rsqrtf(vs * (1.0f/128.0f) + 1e-5f);
        const __half2 h01 = __floats2half2_rn(d0*rs*gm.x + bt.x, d1*rs*gm.y + bt.y);
        const __half2 h23 = __floats2half2_rn(d2*rs*gm.z + bt.z, d3*rs*gm.w + bt.w);
        char* dst = smc + lt*XSB + lane*8;
        *(__half2*)(dst)     = h01;
        *(__half2*)(dst + 4) = h23;
    }
    __syncthreads();

    // ---- tri-bias projection -> multiplicative ex2 form (2^-6 safety shift) ----
    {
        const int lt = tid & 127;
        const int h0 = (tid >> 7) * 2;
        #pragma unroll
        for (int hh = 0; hh < 2; hh++) {
            const int h = h0 + hh;
            float sacc = 0.f;
            #pragma unroll 8
            for (int c0 = 0; c0 < CIN; c0 += 2) {
                const float2 xf = __half22float2(*(const __half2*)(smc + lt*XSB + c0*2));
                const float2 wv = *(const float2*)(wbias + h*CIN + c0);
                sacc += xf.x*wv.x + xf.y*wv.y;
            }
            g_eb[h*NTOK + t0 + lt] = ex2(sacc * LOG2E - 6.0f);
        }
    }

    // ---- A fragments ----
    const int m0 = warp * 16;
    uint32_t a[8][4];
    #pragma unroll
    for (int ks = 0; ks < 8; ks++) {
        const char* rp = smc + (m0+gr)*XSB + ks*32 + gc*4;
        a[ks][0] = *(const uint32_t*)(rp);
        a[ks][1] = *(const uint32_t*)(rp + 8*XSB);
        a[ks][2] = *(const uint32_t*)(rp + 16);
        a[ks][3] = *(const uint32_t*)(rp + 8*XSB + 16);
    }
    __syncthreads();

    const uint32_t wbu[2] = { s2u(wb[0]), s2u(wb[1]) };
    #pragma unroll
    for (int q = 0; q < 2; q++) {
        const __half* src = g_wh + q*8192;
        #pragma unroll
        for (int s = 0; s < 4; s++) {
            const int idx = tid + 256*s;
            const int o = idx >> 4, ch = idx & 15;
            cpa16(wbu[q] + o*WSB + ch*16, src + o*128 + ch*8);
        }
        CPA_COMMIT();
    }

    const int i_row = t0 / NSEQ;
    const int jb    = t0 % NSEQ;
    const int j0    = jb + m0 + gr;

    for (int p = 0; p < 8; p++) {
        if (p == 7) { CPA_WAIT(0); } else { CPA_WAIT(1); }
        __syncthreads();

        const char* wS = wb[p & 1];
        float acc[8][4];
        #pragma unroll
        for (int nt = 0; nt < 8; nt++)
            #pragma unroll
            for (int e = 0; e < 4; e++) acc[nt][e] = 0.f;

        #pragma unroll
        for (int ks = 0; ks < 8; ks++) {
            #pragma unroll
            for (int nt = 0; nt < 8; nt++) {
                const uint2 b = *(const uint2*)(wS + (nt*8+gr)*WSB + ks*32 + gc*8);
                mma_f16(acc[nt], a[ks][0], a[ks][1], a[ks][2], a[ks][3], b.x, b.y);
            }
        }
        __syncthreads();

        if (p + 2 < 8) {
            const __half* src = g_wh + (p+2)*8192;
            #pragma unroll
            for (int s = 0; s < 4; s++) {
                const int idx = tid + 256*s;
                const int o = idx >> 4, ch = idx & 15;
                cpa16(wbu[p & 1] + o*WSB + ch*16, src + o*128 + ch*8);
            }
            CPA_COMMIT();
        }

        // ---- epilogue ----
        const int grp = p >> 1;
        const int ob  = (p & 1) * 64;
        if (grp < 3) {
            __half* dst = (grp==0) ? g_qh : (grp==1) ? g_kh : g_vh;
            const float sc = (grp==0) ? 0.17677669529663687f * LOG2E : 1.0f;
            #pragma unroll
            for (int nt = 0; nt < 8; nt++) {
                const int o = ob + nt*8 + 2*gc;
                const int h = o >> 5, d = o & 31;
                __half* ptr = dst + ((size_t)(i_row*NH + h)*NSEQ + j0)*DH + d;
                *(__half2*)ptr          = __floats2half2_rn(acc[nt][0]*sc, acc[nt][1]*sc);
                *(__half2*)(ptr + 8*DH) = __floats2half2_rn(acc[nt][2]*sc, acc[nt][3]*sc);
            }
        } else {
            const int tok = t0 + m0 + gr;
            #pragma unroll
            for (int nt = 0; nt < 8; nt++) {
                const int o = ob + nt*8 + 2*gc;
                const float2 bgv = __ldg((const float2*)(bg + o));
                const float l0 = 1.0f/(1.0f+__expf(-(acc[nt][0]+bgv.x)));
                const float l1 = 1.0f/(1.0f+__expf(-(acc[nt][1]+bgv.y)));
                const float h0 = 1.0f/(1.0f+__expf(-(acc[nt][2]+bgv.x)));
                const float h1 = 1.0f/(1.0f+__expf(-(acc[nt][3]+bgv.y)));
                *(__half2*)(g_acth + (size_t)tok*CIN + o)     = __floats2half2_rn(l0, l1);
                *(__half2*)(g_acth + (size_t)(tok+8)*CIN + o) = __floats2half2_rn(h0, h1);
            }
        }
    }
}

// ============================================================================
// Kernel 2: flash attention per (i,h), fully fp16 MMA. AV A-frag = QK C-frag.
// Gate read/write fp16.
// ============================================================================
#define K_OFF 0
#define V_OFF (NSEQ*KHB)
#define M_OFF (V_OFF + DH*VSTH*2)
#define K2_SMEM (M_OFF + NSEQ*4)

__global__ __launch_bounds__(384, 2) void k2_attn(const float* __restrict__ mask)
{
    extern __shared__ char smc[];
    __half* Ksm = (__half*)(smc + K_OFF);
    __half* VT  = (__half*)(smc + V_OFF);
    float*  msm = (float*)(smc + M_OFF);

    const int tid  = threadIdx.x;
    const int warp = tid >> 5, lane = tid & 31;
    const int gr   = lane >> 2, gc = lane & 3;
    const int i = blockIdx.x >> 2;
    const int h = blockIdx.x & 3;
    const int base = ((i*NH) + h) * NSEQ * DH;

    {
        const uint32_t ku = s2u(Ksm);
        #pragma unroll
        for (int it = 0; it < 4; it++) {
            const int idx = tid + 384*it;
            const int j = idx >> 2, ch = idx & 3;
            cpa16(ku + j*KHB + ch*16, g_kh + base + j*DH + ch*8);
        }
        CPA_COMMIT();
    }
    #pragma unroll
    for (int it = 0; it < 16; it++) {
        const int idx = tid + 384*it;
        const int j = idx >> 4, dp = idx & 15;
        const __half2 hv = *(const __half2*)(g_vh + base + j*DH + dp*2);
        VT[(2*dp)*VSTH + j]   = __low2half(hv);
        VT[(2*dp+1)*VSTH + j] = __high2half(hv);
    }
    if (tid < NSEQ)
        msm[tid] = ex2((mask[i*NSEQ + tid] - 1.0f) * (1e9f * LOG2E));
    CPA_WAIT(0);
    __syncthreads();

    const float* __restrict__ tb = g_eb + h*NTOK;
    const uint32_t* vt32 = (const uint32_t*)VT;

    for (int t = 0; t < 2; t++) {
        const int jq0 = (warp + 12*t) * 16;

        uint32_t qa[2][4];
        const uint32_t* qp  = (const uint32_t*)(g_qh + base + (jq0+gr)*DH);
        const uint32_t* qp8 = qp + 8*(DH/2);
        #pragma unroll
        for (int ks = 0; ks < 2; ks++) {
            qa[ks][0] = __ldg(qp  + ks*8 + gc);
            qa[ks][1] = __ldg(qp8 + ks*8 + gc);
            qa[ks][2] = __ldg(qp  + ks*8 + gc + 4);
            qa[ks][3] = __ldg(qp8 + ks*8 + gc + 4);
        }

        float s0 = 0.f, s1 = 0.f;
        float o[4][4];
        #pragma unroll
        for (int j = 0; j < 4; j++)
            #pragma unroll
            for (int e = 0; e < 4; e++) o[j][e] = 0.f;

        const float* tbr0 = tb + (size_t)(jq0+gr)*NSEQ;
        const float* tbr1 = tbr0 + 8*NSEQ;

        for (int n0 = 0; n0 < NSEQ; n0 += 32) {
            float c[4][4];
            #pragma unroll
            for (int j = 0; j < 4; j++) {
                #pragma unroll
                for (int e = 0; e < 4; e++) c[j][e] = 0.f;
                const uint32_t* kb =
                    (const uint32_t*)((const char*)Ksm + (n0 + 8*j + gr)*KHB);
                #pragma unroll
                for (int ks = 0; ks < 2; ks++) {
                    const uint32_t b0 = kb[ks*8 + gc];
                    const uint32_t b1 = kb[ks*8 + gc + 4];
                    mma_f16(c[j], qa[ks][0], qa[ks][1], qa[ks][2], qa[ks][3], b0, b1);
                }
            }

            #pragma unroll
            for (int j = 0; j < 4; j++) {
                const float2 e0 = __ldg((const float2*)(tbr0 + n0 + 8*j + 2*gc));
                const float2 e1 = __ldg((const float2*)(tbr1 + n0 + 8*j + 2*gc));
                const float2 mk = *(const float2*)(msm + n0 + 8*j + 2*gc);
                const float p0 = ex2(c[j][0]) * (e0.x*mk.x);
                const float p1 = ex2(c[j][1]) * (e0.y*mk.y);
                const float p2 = ex2(c[j][2]) * (e1.x*mk.x);
                const float p3 = ex2(c[j][3]) * (e1.y*mk.y);
                s0 += p0 + p1; s1 += p2 + p3;
                c[j][0] = p0; c[j][1] = p1; c[j][2] = p2; c[j][3] = p3;
            }

            #pragma unroll
            for (int ks = 0; ks < 2; ks++) {
                const uint32_t a0 = pkh2(c[2*ks  ][0], c[2*ks  ][1]);
                const uint32_t a1 = pkh2(c[2*ks  ][2], c[2*ks  ][3]);
                const uint32_t a2 = pkh2(c[2*ks+1][0], c[2*ks+1][1]);
                const uint32_t a3 = pkh2(c[2*ks+1][2], c[2*ks+1][3]);
                const int kk = (n0 + 16*ks) >> 1;
                #pragma unroll
                for (int j = 0; j < 4; j++) {
                    const uint32_t* vr = vt32 + (8*j + gr)*(VSTH/2) + kk;
                    mma_f16(o[j], a0, a1, a2, a3, vr[gc], vr[gc + 4]);
                }
            }
        }

        s0 += __shfl_xor_sync(0xffffffffu, s0, 1);
        s0 += __shfl_xor_sync(0xffffffffu, s0, 2);
        s1 += __shfl_xor_sync(0xffffffffu, s1, 1);
        s1 += __shfl_xor_sync(0xffffffffu, s1, 2);
        const float inv0 = 1.0f / s0, inv1 = 1.0f / s1;

        #pragma unroll
        for (int j = 0; j < 4; j++) {
            const int col = h*DH + 8*j + 2*gc;
            const size_t r0 = (size_t)(i*NSEQ + jq0 + gr)*CIN + col;
            const size_t r1 = (size_t)(i*NSEQ + jq0 + gr + 8)*CIN + col;
            const float2 g0 = __half22float2(*(const __half2*)(g_acth + r0));
            const float2 g1 = __half22float2(*(const __half2*)(g_acth + r1));
            *(__half2*)(g_acth + r0) =
                __floats2half2_rn(o[j][0]*inv0*g0.x, o[j][1]*inv0*g0.y);
            *(__half2*)(g_acth + r1) =
                __floats2half2_rn(o[j][2]*inv1*g1.x, o[j][3]*inv1*g1.y);
        }
    }
}

// ============================================================================
// Kernel 3: out = act @ wo^T + bo  (fp16 mma; act staged via raw cp.async)
// ============================================================================
__global__ __launch_bounds__(256, 2) void k3_out(
    const float* __restrict__ bo, float* __restrict__ out)
{
    extern __shared__ char smc[];
    char* wb[2] = { smc, smc + 64*WSB };

    const int tid  = threadIdx.x;
    const int warp = tid >> 5, lane = tid & 31;
    const int gr   = lane >> 2, gc = lane & 3;
    const int t0   = blockIdx.x * 128;

    const uint32_t xsu = s2u(smc);
    // stage act rows (fp16, 256B each) -> XSB-strided smem, async
    #pragma unroll
    for (int s = 0; s < 8; s++) {
        const int idx = tid + 256*s;              // 2048 chunks of 16B
        const int lt = idx >> 4, ch = idx & 15;
        cpa16(xsu + lt*XSB + ch*16, g_acth + (size_t)(t0+lt)*CIN + ch*8);
    }
    CPA_COMMIT();

    // NOTE: W buffers overlap xs; A-frags must be read before W copies land.
    CPA_WAIT(0);
    __syncthreads();

    const int m0 = warp * 16;
    uint32_t a[8][4];
    #pragma unroll
    for (int ks = 0; ks < 8; ks++) {
        const char* rp = smc + (m0+gr)*XSB + ks*32 + gc*4;
        a[ks][0] = *(const uint32_t*)(rp);
        a[ks][1] = *(const uint32_t*)(rp + 8*XSB);
        a[ks][2] = *(const uint32_t*)(rp + 16);
        a[ks][3] = *(const uint32_t*)(rp + 8*XSB + 16);
    }
    __syncthreads();

    const uint32_t wbu[2] = { s2u(wb[0]), s2u(wb[1]) };
    #pragma unroll
    for (int q = 0; q < 2; q++) {
        const __half* src = g_wh + 4*16384 + q*8192;
        #pragma unroll
        for (int s = 0; s < 4; s++) {
            const int idx = tid + 256*s;
            const int o = idx >> 4, ch = idx & 15;
            cpa16(wbu[q] + o*WSB + ch*16, src + o*128 + ch*8);
        }
        CPA_COMMIT();
    }

    const int tok = t0 + m0 + gr;
    for (int hf = 0; hf < 2; hf++) {
        if (hf == 0) { CPA_WAIT(1); } else { CPA_WAIT(0); }
        __syncthreads();

        const char* wS = wb[hf];
        float acc[8][4];
        #pragma unroll
        for (int nt = 0; nt < 8; nt++)
            #pragma unroll
            for (int e = 0; e < 4; e++) acc[nt][e] = 0.f;

        #pragma unroll
        for (int ks = 0; ks < 8; ks++) {
            #pragma unroll
            for (int nt = 0; nt < 8; nt++) {
                const uint2 b = *(const uint2*)(wS + (nt*8+gr)*WSB + ks*32 + gc*8);
                mma_f16(acc[nt], a[ks][0], a[ks][1], a[ks][2], a[ks][3], b.x, b.y);
            }
        }

        #pragma unroll
        for (int nt = 0; nt < 8; nt++) {
            const int o = hf*64 + nt*8 + 2*gc;
            const float2 bov = __ldg((const float2*)(bo + o));
            *(float2*)(out + (size_t)tok*CIN + o) =
                make_float2(acc[nt][0]+bov.x, acc[nt][1]+bov.y);
            *(float2*)(out + (size_t)(tok+8)*CIN + o) =
                make_float2(acc[nt][2]+bov.x, acc[nt][3]+bov.y);
        }
    }
}

// ============================================================================
extern "C" void kernel_launch(void* const* d_in, const int* in_sizes, int n_in,
                              void* d_out, int out_size)
{
    const float* x     = (const float*)d_in[0];
    const float* mask  = (const float*)d_in[1];
    const float* gamma = (const float*)d_in[2];
    const float* beta  = (const float*)d_in[3];
    const float* wbias = (const float*)d_in[4];
    const float* wq    = (const float*)d_in[5];
    const float* wk    = (const float*)d_in[6];
    const float* wv    = (const float*)d_in[7];
    const float* wg    = (const float*)d_in[8];
    const float* bg    = (const float*)d_in[9];
    const float* wo    = (const float*)d_in[10];
    const float* bo    = (const float*)d_in[11];
    float* out = (float*)d_out;

    const int smem_gemm = 2 * 64 * WSB;           // 36,864 B

    cudaFuncSetAttribute(k1_ln_proj, cudaFuncAttributeMaxDynamicSharedMemorySize, smem_gemm);
    cudaFuncSetAttribute(k2_attn,   cudaFuncAttributeMaxDynamicSharedMemorySize, K2_SMEM);
    cudaFuncSetAttribute(k3_out,    cudaFuncAttributeMaxDynamicSharedMemorySize, smem_gemm);

    k0_prep  <<<320, 256>>>(wq, wk, wv, wg, wo);
    k1_ln_proj<<<NTOK/128, 256, smem_gemm>>>(x, gamma, beta, wbias, bg);
    k2_attn  <<<NSEQ*NH,  384, K2_SMEM>>>(mask);
    k3_out   <<<NTOK/128, 256, smem_gemm>>>(bo, out);
}

// round 16
// speedup vs baseline: 1.0322x; 1.0322x over previous
#include <cuda_runtime.h>
#include <cuda_bf16.h>
#include <cuda_fp16.h>
#include <cstdint>

#define NSEQ 384
#define CIN  128
#define NH   4
#define DH   32
#define NTOK (NSEQ*NSEQ)
#define LOG2E 1.4426950408889634f

// fp16 smem geometry (bytes)
#define XSB 272     // k1/k3 A rows: frag b32 loads bank-perfect
#define WSB 288     // k1/k3 W rows: LDS.64 frag loads bank-perfect
#define KHB 80      // k2 K rows (40 halves): b32 loads bank-perfect
#define VSTH 392    // k2 V^T rows (halves): b32 loads bank-perfect

// ---- helpers ----
__device__ __forceinline__ float ex2(float x) {
    float r; asm("ex2.approx.f32 %0, %1;" : "=f"(r) : "f"(x)); return r;
}
__device__ __forceinline__ void mma_f16(float c[4],
    uint32_t a0, uint32_t a1, uint32_t a2, uint32_t a3, uint32_t b0, uint32_t b1)
{
    asm("mma.sync.aligned.m16n8k16.row.col.f32.f16.f16.f32 "
        "{%0,%1,%2,%3}, {%4,%5,%6,%7}, {%8,%9}, {%0,%1,%2,%3};"
        : "+f"(c[0]), "+f"(c[1]), "+f"(c[2]), "+f"(c[3])
        : "r"(a0), "r"(a1), "r"(a2), "r"(a3), "r"(b0), "r"(b1));
}
__device__ __forceinline__ uint32_t s2u(const void* p) {
    uint32_t a;
    asm("{ .reg .u64 t; cvta.to.shared.u64 t, %1; cvt.u32.u64 %0, t; }" : "=r"(a) : "l"(p));
    return a;
}
__device__ __forceinline__ void cpa16(uint32_t dst, const void* src) {
    asm volatile("cp.async.cg.shared.global [%0], [%1], 16;" :: "r"(dst), "l"(src));
}
#define CPA_COMMIT() asm volatile("cp.async.commit_group;" ::: "memory")
#define CPA_WAIT(n)  asm volatile("cp.async.wait_group %0;" :: "n"(n) : "memory")
__device__ __forceinline__ uint32_t pkh2(float a, float b) {
    __half2 h = __floats2half2_rn(a, b);
    return *(uint32_t*)&h;
}

// ---- scratch ----
__device__ __half g_qh[NSEQ*NH*NSEQ*DH];   // fp16, q pre-scaled by sc*log2e
__device__ __half g_kh[NSEQ*NH*NSEQ*DH];   // fp16
__device__ __half g_vh[NSEQ*NH*NSEQ*DH];   // fp16
__device__ __align__(16) __half g_acth[(size_t)NTOK*CIN];  // fp16 gate -> gated attn out
__device__ float  g_eb [NH*NTOK];          // ex2(tri-bias*log2e - 6)
__device__ __align__(16) __half g_wh [5*CIN*CIN];  // fp16, k-pair permuted weights
__device__ __align__(16) __half g_wbh[8*CIN];      // fp16 wbias (rows 4-7 zero), permuted

// ============================================================================
// Kernel 0: weights -> fp16, k-pair permuted (B frag = one LDS.64).
// Also emits wbias into the padded 8-row tile (rows 4-7 stay zero).
// ============================================================================
__global__ void k0_prep(const float* __restrict__ wq, const float* __restrict__ wk,
                        const float* __restrict__ wv, const float* __restrict__ wg,
                        const float* __restrict__ wo, const float* __restrict__ wbias)
{
    const int idx = blockIdx.x * 256 + threadIdx.x;      // 81920
    const int m   = idx >> 14;
    const int rem = idx & 16383;
    const int o   = rem >> 7, c = rem & 127;
    const float* srcs[5] = {wq, wk, wv, wg, wo};
    const float v = srcs[m][o*CIN + c];
    const int j    = (c >> 1) & 7;
    const int slot = 2*(j & 3) + (j >> 2);
    const int cperm = (c & ~15) | (slot << 1) | (c & 1);
    g_wh[m*16384 + o*128 + cperm] = __float2half_rn(v);

    if (idx < 512) {   // wbias: 4 x 128
        const int ob = idx >> 7, cb = idx & 127;
        const int jb2   = (cb >> 1) & 7;
        const int slot2 = 2*(jb2 & 3) + (jb2 >> 2);
        const int cp2   = (cb & ~15) | (slot2 << 1) | (cb & 1);
        g_wbh[ob*128 + cp2] = __float2half_rn(wbias[ob*CIN + cb]);
    }
}

// ============================================================================
// Kernel 1: LayerNorm + q/k/v/gate projections (fp16 mma) + tri-bias via MMA.
// ============================================================================
__global__ __launch_bounds__(256, 2) void k1_ln_proj(
    const float* __restrict__ x,   const float* __restrict__ gamma,
    const float* __restrict__ beta,const float* __restrict__ bg)
{
    extern __shared__ char smc[];
    char* wb[2] = { smc, smc + 64*WSB };

    const int tid  = threadIdx.x;
    const int warp = tid >> 5, lane = tid & 31;
    const int gr   = lane >> 2, gc = lane & 3;
    const int t0   = blockIdx.x * 128;

    // ---- LayerNorm -> xs (fp16) ----
    const float4 gm = *(const float4*)(gamma + lane*4);
    const float4 bt = *(const float4*)(beta  + lane*4);
    for (int kk = 0; kk < 16; kk++) {
        const int lt = warp*16 + kk;
        const float4 xv = *(const float4*)(x + (size_t)(t0+lt)*CIN + lane*4);
        float s = xv.x + xv.y + xv.z + xv.w;
        #pragma unroll
        for (int o = 16; o; o >>= 1) s += __shfl_xor_sync(0xffffffffu, s, o);
        const float mu = s * (1.0f/128.0f);
        const float d0 = xv.x-mu, d1 = xv.y-mu, d2 = xv.z-mu, d3 = xv.w-mu;
        float vs = d0*d0 + d1*d1 + d2*d2 + d3*d3;
        #pragma unroll
        for (int o = 16; o; o >>= 1) vs += __shfl_xor_sync(0xffffffffu, vs, o);
        const float rs = rsqrtf(vs * (1.0f/128.0f) + 1e-5f);
        const __half2 h01 = __floats2half2_rn(d0*rs*gm.x + bt.x, d1*rs*gm.y + bt.y);
        const __half2 h23 = __floats2half2_rn(d2*rs*gm.z + bt.z, d3*rs*gm.w + bt.w);
        char* dst = smc + lt*XSB + lane*8;
        *(__half2*)(dst)     = h01;
        *(__half2*)(dst + 4) = h23;
    }
    __syncthreads();

    // ---- A fragments ----
    const int m0 = warp * 16;
    uint32_t a[8][4];
    #pragma unroll
    for (int ks = 0; ks < 8; ks++) {
        const char* rp = smc + (m0+gr)*XSB + ks*32 + gc*4;
        a[ks][0] = *(const uint32_t*)(rp);
        a[ks][1] = *(const uint32_t*)(rp + 8*XSB);
        a[ks][2] = *(const uint32_t*)(rp + 16);
        a[ks][3] = *(const uint32_t*)(rp + 8*XSB + 16);
    }
    __syncthreads();

    // ---- W prefetch phases 0,1 (cp.async flows under the bias MMA) ----
    const uint32_t wbu[2] = { s2u(wb[0]), s2u(wb[1]) };
    #pragma unroll
    for (int q = 0; q < 2; q++) {
        const __half* src = g_wh + q*8192;
        #pragma unroll
        for (int s = 0; s < 4; s++) {
            const int idx = tid + 256*s;
            const int o = idx >> 4, ch = idx & 15;
            cpa16(wbu[q] + o*WSB + ch*16, src + o*128 + ch*8);
        }
        CPA_COMMIT();
    }

    // ---- tri-bias via MMA (N=8 padded, B frags from L1-hot global) ----
    {
        float bc[4] = {0.f, 0.f, 0.f, 0.f};
        const char* wbp = (const char*)g_wbh + gr*256 + gc*8;
        #pragma unroll
        for (int ks = 0; ks < 8; ks++) {
            const uint2 b = __ldg((const uint2*)(wbp + ks*32));
            mma_f16(bc, a[ks][0], a[ks][1], a[ks][2], a[ks][3], b.x, b.y);
        }
        if (gc < 2) {
            const int tok = t0 + m0 + gr;
            g_eb[(2*gc  )*NTOK + tok] = ex2(bc[0]*LOG2E - 6.0f);
            g_eb[(2*gc+1)*NTOK + tok] = ex2(bc[1]*LOG2E - 6.0f);
            g_eb[(2*gc  )*NTOK + tok + 8] = ex2(bc[2]*LOG2E - 6.0f);
            g_eb[(2*gc+1)*NTOK + tok + 8] = ex2(bc[3]*LOG2E - 6.0f);
        }
    }

    const int i_row = t0 / NSEQ;
    const int jb    = t0 % NSEQ;
    const int j0    = jb + m0 + gr;

    for (int p = 0; p < 8; p++) {
        if (p == 7) { CPA_WAIT(0); } else { CPA_WAIT(1); }
        __syncthreads();

        const char* wS = wb[p & 1];
        float acc[8][4];
        #pragma unroll
        for (int nt = 0; nt < 8; nt++)
            #pragma unroll
            for (int e = 0; e < 4; e++) acc[nt][e] = 0.f;

        #pragma unroll
        for (int ks = 0; ks < 8; ks++) {
            #pragma unroll
            for (int nt = 0; nt < 8; nt++) {
                const uint2 b = *(const uint2*)(wS + (nt*8+gr)*WSB + ks*32 + gc*8);
                mma_f16(acc[nt], a[ks][0], a[ks][1], a[ks][2], a[ks][3], b.x, b.y);
            }
        }
        __syncthreads();

        if (p + 2 < 8) {
            const __half* src = g_wh + (p+2)*8192;
            #pragma unroll
            for (int s = 0; s < 4; s++) {
                const int idx = tid + 256*s;
                const int o = idx >> 4, ch = idx & 15;
                cpa16(wbu[p & 1] + o*WSB + ch*16, src + o*128 + ch*8);
            }
            CPA_COMMIT();
        }

        // ---- epilogue ----
        const int grp = p >> 1;
        const int ob  = (p & 1) * 64;
        if (grp < 3) {
            __half* dst = (grp==0) ? g_qh : (grp==1) ? g_kh : g_vh;
            const float sc = (grp==0) ? 0.17677669529663687f * LOG2E : 1.0f;
            #pragma unroll
            for (int nt = 0; nt < 8; nt++) {
                const int o = ob + nt*8 + 2*gc;
                const int h = o >> 5, d = o & 31;
                __half* ptr = dst + ((size_t)(i_row*NH + h)*NSEQ + j0)*DH + d;
                *(__half2*)ptr          = __floats2half2_rn(acc[nt][0]*sc, acc[nt][1]*sc);
                *(__half2*)(ptr + 8*DH) = __floats2half2_rn(acc[nt][2]*sc, acc[nt][3]*sc);
            }
        } else {
            const int tok = t0 + m0 + gr;
            #pragma unroll
            for (int nt = 0; nt < 8; nt++) {
                const int o = ob + nt*8 + 2*gc;
                const float2 bgv = __ldg((const float2*)(bg + o));
                const float l0 = 1.0f/(1.0f+__expf(-(acc[nt][0]+bgv.x)));
                const float l1 = 1.0f/(1.0f+__expf(-(acc[nt][1]+bgv.y)));
                const float h0 = 1.0f/(1.0f+__expf(-(acc[nt][2]+bgv.x)));
                const float h1 = 1.0f/(1.0f+__expf(-(acc[nt][3]+bgv.y)));
                *(__half2*)(g_acth + (size_t)tok*CIN + o)     = __floats2half2_rn(l0, l1);
                *(__half2*)(g_acth + (size_t)(tok+8)*CIN + o) = __floats2half2_rn(h0, h1);
            }
        }
    }
}

// ============================================================================
// Kernel 2: flash attention per (i,h), fully fp16 MMA. AV A-frag = QK C-frag.
// ============================================================================
#define K_OFF 0
#define V_OFF (NSEQ*KHB)
#define M_OFF (V_OFF + DH*VSTH*2)
#define K2_SMEM (M_OFF + NSEQ*4)

__global__ __launch_bounds__(384, 2) void k2_attn(const float* __restrict__ mask)
{
    extern __shared__ char smc[];
    __half* Ksm = (__half*)(smc + K_OFF);
    __half* VT  = (__half*)(smc + V_OFF);
    float*  msm = (float*)(smc + M_OFF);

    const int tid  = threadIdx.x;
    const int warp = tid >> 5, lane = tid & 31;
    const int gr   = lane >> 2, gc = lane & 3;
    const int i = blockIdx.x >> 2;
    const int h = blockIdx.x & 3;
    const int base = ((i*NH) + h) * NSEQ * DH;

    {
        const uint32_t ku = s2u(Ksm);
        #pragma unroll
        for (int it = 0; it < 4; it++) {
            const int idx = tid + 384*it;
            const int j = idx >> 2, ch = idx & 3;
            cpa16(ku + j*KHB + ch*16, g_kh + base + j*DH + ch*8);
        }
        CPA_COMMIT();
    }
    #pragma unroll
    for (int it = 0; it < 16; it++) {
        const int idx = tid + 384*it;
        const int j = idx >> 4, dp = idx & 15;
        const __half2 hv = *(const __half2*)(g_vh + base + j*DH + dp*2);
        VT[(2*dp)*VSTH + j]   = __low2half(hv);
        VT[(2*dp+1)*VSTH + j] = __high2half(hv);
    }
    if (tid < NSEQ)
        msm[tid] = ex2((mask[i*NSEQ + tid] - 1.0f) * (1e9f * LOG2E));
    CPA_WAIT(0);
    __syncthreads();

    const float* __restrict__ tb = g_eb + h*NTOK;
    const uint32_t* vt32 = (const uint32_t*)VT;

    for (int t = 0; t < 2; t++) {
        const int jq0 = (warp + 12*t) * 16;

        uint32_t qa[2][4];
        const uint32_t* qp  = (const uint32_t*)(g_qh + base + (jq0+gr)*DH);
        const uint32_t* qp8 = qp + 8*(DH/2);
        #pragma unroll
        for (int ks = 0; ks < 2; ks++) {
            qa[ks][0] = __ldg(qp  + ks*8 + gc);
            qa[ks][1] = __ldg(qp8 + ks*8 + gc);
            qa[ks][2] = __ldg(qp  + ks*8 + gc + 4);
            qa[ks][3] = __ldg(qp8 + ks*8 + gc + 4);
        }

        float s0 = 0.f, s1 = 0.f;
        float o[4][4];
        #pragma unroll
        for (int j = 0; j < 4; j++)
            #pragma unroll
            for (int e = 0; e < 4; e++) o[j][e] = 0.f;

        const float* tbr0 = tb + (size_t)(jq0+gr)*NSEQ;
        const float* tbr1 = tbr0 + 8*NSEQ;

        for (int n0 = 0; n0 < NSEQ; n0 += 32) {
            float c[4][4];
            #pragma unroll
            for (int j = 0; j < 4; j++) {
                #pragma unroll
                for (int e = 0; e < 4; e++) c[j][e] = 0.f;
                const uint32_t* kb =
                    (const uint32_t*)((const char*)Ksm + (n0 + 8*j + gr)*KHB);
                #pragma unroll
                for (int ks = 0; ks < 2; ks++) {
                    const uint32_t b0 = kb[ks*8 + gc];
                    const uint32_t b1 = kb[ks*8 + gc + 4];
                    mma_f16(c[j], qa[ks][0], qa[ks][1], qa[ks][2], qa[ks][3], b0, b1);
                }
            }

            #pragma unroll
            for (int j = 0; j < 4; j++) {
                const float2 e0 = __ldg((const float2*)(tbr0 + n0 + 8*j + 2*gc));
                const float2 e1 = __ldg((const float2*)(tbr1 + n0 + 8*j + 2*gc));
                const float2 mk = *(const float2*)(msm + n0 + 8*j + 2*gc);
                const float p0 = ex2(c[j][0]) * (e0.x*mk.x);
                const float p1 = ex2(c[j][1]) * (e0.y*mk.y);
                const float p2 = ex2(c[j][2]) * (e1.x*mk.x);
                const float p3 = ex2(c[j][3]) * (e1.y*mk.y);
                s0 += p0 + p1; s1 += p2 + p3;
                c[j][0] = p0; c[j][1] = p1; c[j][2] = p2; c[j][3] = p3;
            }

            #pragma unroll
            for (int ks = 0; ks < 2; ks++) {
                const uint32_t a0 = pkh2(c[2*ks  ][0], c[2*ks  ][1]);
                const uint32_t a1 = pkh2(c[2*ks  ][2], c[2*ks  ][3]);
                const uint32_t a2 = pkh2(c[2*ks+1][0], c[2*ks+1][1]);
                const uint32_t a3 = pkh2(c[2*ks+1][2], c[2*ks+1][3]);
                const int kk = (n0 + 16*ks) >> 1;
                #pragma unroll
                for (int j = 0; j < 4; j++) {
                    const uint32_t* vr = vt32 + (8*j + gr)*(VSTH/2) + kk;
                    mma_f16(o[j], a0, a1, a2, a3, vr[gc], vr[gc + 4]);
                }
            }
        }

        s0 += __shfl_xor_sync(0xffffffffu, s0, 1);
        s0 += __shfl_xor_sync(0xffffffffu, s0, 2);
        s1 += __shfl_xor_sync(0xffffffffu, s1, 1);
        s1 += __shfl_xor_sync(0xffffffffu, s1, 2);
        const float inv0 = 1.0f / s0, inv1 = 1.0f / s1;

        #pragma unroll
        for (int j = 0; j < 4; j++) {
            const int col = h*DH + 8*j + 2*gc;
            const size_t r0 = (size_t)(i*NSEQ + jq0 + gr)*CIN + col;
            const size_t r1 = (size_t)(i*NSEQ + jq0 + gr + 8)*CIN + col;
            const float2 g0 = __half22float2(*(const __half2*)(g_acth + r0));
            const float2 g1 = __half22float2(*(const __half2*)(g_acth + r1));
            *(__half2*)(g_acth + r0) =
                __floats2half2_rn(o[j][0]*inv0*g0.x, o[j][1]*inv0*g0.y);
            *(__half2*)(g_acth + r1) =
                __floats2half2_rn(o[j][2]*inv1*g1.x, o[j][3]*inv1*g1.y);
        }
    }
}

// ============================================================================
// Kernel 3: out = act @ wo^T + bo  (fp16 mma; act staged via raw cp.async)
// ============================================================================
__global__ __launch_bounds__(256, 2) void k3_out(
    const float* __restrict__ bo, float* __restrict__ out)
{
    extern __shared__ char smc[];
    char* wb[2] = { smc, smc + 64*WSB };

    const int tid  = threadIdx.x;
    const int warp = tid >> 5, lane = tid & 31;
    const int gr   = lane >> 2, gc = lane & 3;
    const int t0   = blockIdx.x * 128;

    const uint32_t xsu = s2u(smc);
    #pragma unroll
    for (int s = 0; s < 8; s++) {
        const int idx = tid + 256*s;
        const int lt = idx >> 4, ch = idx & 15;
        cpa16(xsu + lt*XSB + ch*16, g_acth + (size_t)(t0+lt)*CIN + ch*8);
    }
    CPA_COMMIT();
    CPA_WAIT(0);
    __syncthreads();

    const int m0 = warp * 16;
    uint32_t a[8][4];
    #pragma unroll
    for (int ks = 0; ks < 8; ks++) {
        const char* rp = smc + (m0+gr)*XSB + ks*32 + gc*4;
        a[ks][0] = *(const uint32_t*)(rp);
        a[ks][1] = *(const uint32_t*)(rp + 8*XSB);
        a[ks][2] = *(const uint32_t*)(rp + 16);
        a[ks][3] = *(const uint32_t*)(rp + 8*XSB + 16);
    }
    __syncthreads();

    const uint32_t wbu[2] = { s2u(wb[0]), s2u(wb[1]) };
    #pragma unroll
    for (int q = 0; q < 2; q++) {
        const __half* src = g_wh + 4*16384 + q*8192;
        #pragma unroll
        for (int s = 0; s < 4; s++) {
            const int idx = tid + 256*s;
            const int o = idx >> 4, ch = idx & 15;
            cpa16(wbu[q] + o*WSB + ch*16, src + o*128 + ch*8);
        }
        CPA_COMMIT();
    }

    const int tok = t0 + m0 + gr;
    for (int hf = 0; hf < 2; hf++) {
        if (hf == 0) { CPA_WAIT(1); } else { CPA_WAIT(0); }
        __syncthreads();

        const char* wS = wb[hf];
        float acc[8][4];
        #pragma unroll
        for (int nt = 0; nt < 8; nt++)
            #pragma unroll
            for (int e = 0; e < 4; e++) acc[nt][e] = 0.f;

        #pragma unroll
        for (int ks = 0; ks < 8; ks++) {
            #pragma unroll
            for (int nt = 0; nt < 8; nt++) {
                const uint2 b = *(const uint2*)(wS + (nt*8+gr)*WSB + ks*32 + gc*8);
                mma_f16(acc[nt], a[ks][0], a[ks][1], a[ks][2], a[ks][3], b.x, b.y);
            }
        }

        #pragma unroll
        for (int nt = 0; nt < 8; nt++) {
            const int o = hf*64 + nt*8 + 2*gc;
            const float2 bov = __ldg((const float2*)(bo + o));
            *(float2*)(out + (size_t)tok*CIN + o) =
                make_float2(acc[nt][0]+bov.x, acc[nt][1]+bov.y);
            *(float2*)(out + (size_t)(tok+8)*CIN + o) =
                make_float2(acc[nt][2]+bov.x, acc[nt][3]+bov.y);
        }
    }
}

// ============================================================================
extern "C" void kernel_launch(void* const* d_in, const int* in_sizes, int n_in,
                              void* d_out, int out_size)
{
    const float* x     = (const float*)d_in[0];
    const float* mask  = (const float*)d_in[1];
    const float* gamma = (const float*)d_in[2];
    const float* beta  = (const float*)d_in[3];
    const float* wbias = (const float*)d_in[4];
    const float* wq    = (const float*)d_in[5];
    const float* wk    = (const float*)d_in[6];
    const float* wv    = (const float*)d_in[7];
    const float* wg    = (const float*)d_in[8];
    const float* bg    = (const float*)d_in[9];
    const float* wo    = (const float*)d_in[10];
    const float* bo    = (const float*)d_in[11];
    float* out = (float*)d_out;

    const int smem_gemm = 2 * 64 * WSB;           // 36,864 B

    cudaFuncSetAttribute(k1_ln_proj, cudaFuncAttributeMaxDynamicSharedMemorySize, smem_gemm);
    cudaFuncSetAttribute(k2_attn,   cudaFuncAttributeMaxDynamicSharedMemorySize, K2_SMEM);
    cudaFuncSetAttribute(k3_out,    cudaFuncAttributeMaxDynamicSharedMemorySize, smem_gemm);

    k0_prep  <<<320, 256>>>(wq, wk, wv, wg, wo, wbias);
    k1_ln_proj<<<NTOK/128, 256, smem_gemm>>>(x, gamma, beta, bg);
    k2_attn  <<<NSEQ*NH,  384, K2_SMEM>>>(mask);
    k3_out   <<<NTOK/128, 256, smem_gemm>>>(bo, out);
}

// round 17
// speedup vs baseline: 1.0382x; 1.0059x over previous
#include <cuda_runtime.h>
#include <cuda_bf16.h>
#include <cuda_fp16.h>
#include <cstdint>

#define NSEQ 384
#define CIN  128
#define NH   4
#define DH   32
#define NTOK (NSEQ*NSEQ)
#define LOG2E 1.4426950408889634f

// fp16 smem geometry (bytes)
#define XSB 272     // k1/k3 A rows: frag b32 loads bank-perfect
#define WSB 288     // k1/k3 W rows: LDS.64 frag loads bank-perfect
#define KHB 80      // k2 K rows (40 halves): b32 loads bank-perfect
#define VSTH 392    // k2 V^T rows (halves): b32 loads bank-perfect

// ---- helpers ----
__device__ __forceinline__ float ex2(float x) {
    float r; asm("ex2.approx.f32 %0, %1;" : "=f"(r) : "f"(x)); return r;
}
__device__ __forceinline__ void mma_f16(float c[4],
    uint32_t a0, uint32_t a1, uint32_t a2, uint32_t a3, uint32_t b0, uint32_t b1)
{
    asm("mma.sync.aligned.m16n8k16.row.col.f32.f16.f16.f32 "
        "{%0,%1,%2,%3}, {%4,%5,%6,%7}, {%8,%9}, {%0,%1,%2,%3};"
        : "+f"(c[0]), "+f"(c[1]), "+f"(c[2]), "+f"(c[3])
        : "r"(a0), "r"(a1), "r"(a2), "r"(a3), "r"(b0), "r"(b1));
}
__device__ __forceinline__ uint32_t s2u(const void* p) {
    uint32_t a;
    asm("{ .reg .u64 t; cvta.to.shared.u64 t, %1; cvt.u32.u64 %0, t; }" : "=r"(a) : "l"(p));
    return a;
}
__device__ __forceinline__ void cpa16(uint32_t dst, const void* src) {
    asm volatile("cp.async.cg.shared.global [%0], [%1], 16;" :: "r"(dst), "l"(src));
}
#define CPA_COMMIT() asm volatile("cp.async.commit_group;" ::: "memory")
#define CPA_WAIT(n)  asm volatile("cp.async.wait_group %0;" :: "n"(n) : "memory")
__device__ __forceinline__ uint32_t pkh2(float a, float b) {
    __half2 h = __floats2half2_rn(a, b);
    return *(uint32_t*)&h;
}

// ---- scratch ----
__device__ __half g_qh[NSEQ*NH*NSEQ*DH];   // fp16, q pre-scaled by sc*log2e
__device__ __half g_kh[NSEQ*NH*NSEQ*DH];   // fp16
__device__ __half g_vh[NSEQ*NH*NSEQ*DH];   // fp16
__device__ __align__(16) __half g_acth[(size_t)NTOK*CIN];  // fp16 gate -> gated attn out
__device__ __half g_ebh[NH*NTOK];          // fp16 ex2(tri-bias*log2e - 6)
__device__ __align__(16) __half g_wh [5*CIN*CIN];  // fp16, k-pair permuted weights
__device__ __align__(16) __half g_wbh[8*CIN];      // fp16 wbias (rows 4-7 zero), permuted

// ============================================================================
// Kernel 0: weights -> fp16, k-pair permuted (B frag = one LDS.64).
// ============================================================================
__global__ void k0_prep(const float* __restrict__ wq, const float* __restrict__ wk,
                        const float* __restrict__ wv, const float* __restrict__ wg,
                        const float* __restrict__ wo, const float* __restrict__ wbias)
{
    const int idx = blockIdx.x * 256 + threadIdx.x;      // 81920
    const int m   = idx >> 14;
    const int rem = idx & 16383;
    const int o   = rem >> 7, c = rem & 127;
    const float* srcs[5] = {wq, wk, wv, wg, wo};
    const float v = srcs[m][o*CIN + c];
    const int j    = (c >> 1) & 7;
    const int slot = 2*(j & 3) + (j >> 2);
    const int cperm = (c & ~15) | (slot << 1) | (c & 1);
    g_wh[m*16384 + o*128 + cperm] = __float2half_rn(v);

    if (idx < 512) {   // wbias: 4 x 128
        const int ob = idx >> 7, cb = idx & 127;
        const int jb2   = (cb >> 1) & 7;
        const int slot2 = 2*(jb2 & 3) + (jb2 >> 2);
        const int cp2   = (cb & ~15) | (slot2 << 1) | (cb & 1);
        g_wbh[ob*128 + cp2] = __float2half_rn(wbias[ob*CIN + cb]);
    }
}

// ============================================================================
// Kernel 1: LayerNorm + q/k/v/gate projections (fp16 mma) + tri-bias via MMA.
// ============================================================================
__global__ __launch_bounds__(256, 2) void k1_ln_proj(
    const float* __restrict__ x,   const float* __restrict__ gamma,
    const float* __restrict__ beta,const float* __restrict__ bg)
{
    extern __shared__ char smc[];
    char* wb[2] = { smc, smc + 64*WSB };

    const int tid  = threadIdx.x;
    const int warp = tid >> 5, lane = tid & 31;
    const int gr   = lane >> 2, gc = lane & 3;
    const int t0   = blockIdx.x * 128;

    // ---- LayerNorm -> xs (fp16) ----
    const float4 gm = *(const float4*)(gamma + lane*4);
    const float4 bt = *(const float4*)(beta  + lane*4);
    for (int kk = 0; kk < 16; kk++) {
        const int lt = warp*16 + kk;
        const float4 xv = *(const float4*)(x + (size_t)(t0+lt)*CIN + lane*4);
        float s = xv.x + xv.y + xv.z + xv.w;
        #pragma unroll
        for (int o = 16; o; o >>= 1) s += __shfl_xor_sync(0xffffffffu, s, o);
        const float mu = s * (1.0f/128.0f);
        const float d0 = xv.x-mu, d1 = xv.y-mu, d2 = xv.z-mu, d3 = xv.w-mu;
        float vs = d0*d0 + d1*d1 + d2*d2 + d3*d3;
        #pragma unroll
        for (int o = 16; o; o >>= 1) vs += __shfl_xor_sync(0xffffffffu, vs, o);
        const float rs = rsqrtf(vs * (1.0f/128.0f) + 1e-5f);
        const __half2 h01 = __floats2half2_rn(d0*rs*gm.x + bt.x, d1*rs*gm.y + bt.y);
        const __half2 h23 = __floats2half2_rn(d2*rs*gm.z + bt.z, d3*rs*gm.w + bt.w);
        char* dst = smc + lt*XSB + lane*8;
        *(__half2*)(dst)     = h01;
        *(__half2*)(dst + 4) = h23;
    }
    __syncthreads();

    // ---- A fragments ----
    const int m0 = warp * 16;
    uint32_t a[8][4];
    #pragma unroll
    for (int ks = 0; ks < 8; ks++) {
        const char* rp = smc + (m0+gr)*XSB + ks*32 + gc*4;
        a[ks][0] = *(const uint32_t*)(rp);
        a[ks][1] = *(const uint32_t*)(rp + 8*XSB);
        a[ks][2] = *(const uint32_t*)(rp + 16);
        a[ks][3] = *(const uint32_t*)(rp + 8*XSB + 16);
    }
    __syncthreads();

    // ---- W prefetch phases 0,1 ----
    const uint32_t wbu[2] = { s2u(wb[0]), s2u(wb[1]) };
    #pragma unroll
    for (int q = 0; q < 2; q++) {
        const __half* src = g_wh + q*8192;
        #pragma unroll
        for (int s = 0; s < 4; s++) {
            const int idx = tid + 256*s;
            const int o = idx >> 4, ch = idx & 15;
            cpa16(wbu[q] + o*WSB + ch*16, src + o*128 + ch*8);
        }
        CPA_COMMIT();
    }

    // ---- tri-bias via MMA (N=8 padded) ----
    {
        float bc[4] = {0.f, 0.f, 0.f, 0.f};
        const char* wbp = (const char*)g_wbh + gr*256 + gc*8;
        #pragma unroll
        for (int ks = 0; ks < 8; ks++) {
            const uint2 b = __ldg((const uint2*)(wbp + ks*32));
            mma_f16(bc, a[ks][0], a[ks][1], a[ks][2], a[ks][3], b.x, b.y);
        }
        if (gc < 2) {
            const int tok = t0 + m0 + gr;
            g_ebh[(2*gc  )*NTOK + tok]     = __float2half_rn(ex2(bc[0]*LOG2E - 6.0f));
            g_ebh[(2*gc+1)*NTOK + tok]     = __float2half_rn(ex2(bc[1]*LOG2E - 6.0f));
            g_ebh[(2*gc  )*NTOK + tok + 8] = __float2half_rn(ex2(bc[2]*LOG2E - 6.0f));
            g_ebh[(2*gc+1)*NTOK + tok + 8] = __float2half_rn(ex2(bc[3]*LOG2E - 6.0f));
        }
    }

    const int i_row = t0 / NSEQ;
    const int jb    = t0 % NSEQ;
    const int j0    = jb + m0 + gr;

    for (int p = 0; p < 8; p++) {
        if (p == 7) { CPA_WAIT(0); } else { CPA_WAIT(1); }
        __syncthreads();

        const char* wS = wb[p & 1];
        float acc[8][4];
        #pragma unroll
        for (int nt = 0; nt < 8; nt++)
            #pragma unroll
            for (int e = 0; e < 4; e++) acc[nt][e] = 0.f;

        #pragma unroll
        for (int ks = 0; ks < 8; ks++) {
            #pragma unroll
            for (int nt = 0; nt < 8; nt++) {
                const uint2 b = *(const uint2*)(wS + (nt*8+gr)*WSB + ks*32 + gc*8);
                mma_f16(acc[nt], a[ks][0], a[ks][1], a[ks][2], a[ks][3], b.x, b.y);
            }
        }
        __syncthreads();

        if (p + 2 < 8) {
            const __half* src = g_wh + (p+2)*8192;
            #pragma unroll
            for (int s = 0; s < 4; s++) {
                const int idx = tid + 256*s;
                const int o = idx >> 4, ch = idx & 15;
                cpa16(wbu[p & 1] + o*WSB + ch*16, src + o*128 + ch*8);
            }
            CPA_COMMIT();
        }

        // ---- epilogue ----
        const int grp = p >> 1;
        const int ob  = (p & 1) * 64;
        if (grp < 3) {
            __half* dst = (grp==0) ? g_qh : (grp==1) ? g_kh : g_vh;
            const float sc = (grp==0) ? 0.17677669529663687f * LOG2E : 1.0f;
            #pragma unroll
            for (int nt = 0; nt < 8; nt++) {
                const int o = ob + nt*8 + 2*gc;
                const int h = o >> 5, d = o & 31;
                __half* ptr = dst + ((size_t)(i_row*NH + h)*NSEQ + j0)*DH + d;
                *(__half2*)ptr          = __floats2half2_rn(acc[nt][0]*sc, acc[nt][1]*sc);
                *(__half2*)(ptr + 8*DH) = __floats2half2_rn(acc[nt][2]*sc, acc[nt][3]*sc);
            }
        } else {
            const int tok = t0 + m0 + gr;
            #pragma unroll
            for (int nt = 0; nt < 8; nt++) {
                const int o = ob + nt*8 + 2*gc;
                const float2 bgv = __ldg((const float2*)(bg + o));
                const float l0 = 1.0f/(1.0f+__expf(-(acc[nt][0]+bgv.x)));
                const float l1 = 1.0f/(1.0f+__expf(-(acc[nt][1]+bgv.y)));
                const float h0 = 1.0f/(1.0f+__expf(-(acc[nt][2]+bgv.x)));
                const float h1 = 1.0f/(1.0f+__expf(-(acc[nt][3]+bgv.y)));
                *(__half2*)(g_acth + (size_t)tok*CIN + o)     = __floats2half2_rn(l0, l1);
                *(__half2*)(g_acth + (size_t)(tok+8)*CIN + o) = __floats2half2_rn(h0, h1);
            }
        }
    }
}

// ============================================================================
// Kernel 2: flash attention per (i,h), fully fp16 MMA. AV A-frag = QK C-frag.
// eb fp16 (halved L2 stream); row sums via ones-column MMA (V^T rows 32..39).
// ============================================================================
#define K_OFF 0
#define V_OFF (NSEQ*KHB)                 // 30720
#define M_OFF (V_OFF + 40*VSTH*2)        // +31360 = 62080
#define K2_SMEM (M_OFF + NSEQ*4)         // 63616

__global__ __launch_bounds__(384, 2) void k2_attn(const float* __restrict__ mask)
{
    extern __shared__ char smc[];
    __half* Ksm = (__half*)(smc + K_OFF);
    __half* VT  = (__half*)(smc + V_OFF);
    float*  msm = (float*)(smc + M_OFF);

    const int tid  = threadIdx.x;
    const int warp = tid >> 5, lane = tid & 31;
    const int gr   = lane >> 2, gc = lane & 3;
    const int i = blockIdx.x >> 2;
    const int h = blockIdx.x & 3;
    const int base = ((i*NH) + h) * NSEQ * DH;

    {
        const uint32_t ku = s2u(Ksm);
        #pragma unroll
        for (int it = 0; it < 4; it++) {
            const int idx = tid + 384*it;
            const int j = idx >> 2, ch = idx & 3;
            cpa16(ku + j*KHB + ch*16, g_kh + base + j*DH + ch*8);
        }
        CPA_COMMIT();
    }
    #pragma unroll
    for (int it = 0; it < 16; it++) {
        const int idx = tid + 384*it;
        const int j = idx >> 4, dp = idx & 15;
        const __half2 hv = *(const __half2*)(g_vh + base + j*DH + dp*2);
        VT[(2*dp)*VSTH + j]   = __low2half(hv);
        VT[(2*dp+1)*VSTH + j] = __high2half(hv);
    }
    // ones/zero rows for row-sum MMA: row 32 = 1, rows 33..39 = 0
    for (int idx = tid; idx < 8*VSTH; idx += 384)
        VT[32*VSTH + idx] = (idx < VSTH) ? __float2half_rn(1.0f) : __float2half_rn(0.0f);
    if (tid < NSEQ)
        msm[tid] = ex2((mask[i*NSEQ + tid] - 1.0f) * (1e9f * LOG2E));
    CPA_WAIT(0);
    __syncthreads();

    const __half* __restrict__ tb = g_ebh + h*NTOK;
    const uint32_t* vt32 = (const uint32_t*)VT;

    for (int t = 0; t < 2; t++) {
        const int jq0 = (warp + 12*t) * 16;

        uint32_t qa[2][4];
        const uint32_t* qp  = (const uint32_t*)(g_qh + base + (jq0+gr)*DH);
        const uint32_t* qp8 = qp + 8*(DH/2);
        #pragma unroll
        for (int ks = 0; ks < 2; ks++) {
            qa[ks][0] = __ldg(qp  + ks*8 + gc);
            qa[ks][1] = __ldg(qp8 + ks*8 + gc);
            qa[ks][2] = __ldg(qp  + ks*8 + gc + 4);
            qa[ks][3] = __ldg(qp8 + ks*8 + gc + 4);
        }

        float o[4][4], o4[4];
        #pragma unroll
        for (int j = 0; j < 4; j++)
            #pragma unroll
            for (int e = 0; e < 4; e++) o[j][e] = 0.f;
        #pragma unroll
        for (int e = 0; e < 4; e++) o4[e] = 0.f;

        const __half* tbr0 = tb + (size_t)(jq0+gr)*NSEQ;
        const __half* tbr1 = tbr0 + 8*NSEQ;

        for (int n0 = 0; n0 < NSEQ; n0 += 32) {
            float c[4][4];
            #pragma unroll
            for (int j = 0; j < 4; j++) {
                #pragma unroll
                for (int e = 0; e < 4; e++) c[j][e] = 0.f;
                const uint32_t* kb =
                    (const uint32_t*)((const char*)Ksm + (n0 + 8*j + gr)*KHB);
                #pragma unroll
                for (int ks = 0; ks < 2; ks++) {
                    const uint32_t b0 = kb[ks*8 + gc];
                    const uint32_t b1 = kb[ks*8 + gc + 4];
                    mma_f16(c[j], qa[ks][0], qa[ks][1], qa[ks][2], qa[ks][3], b0, b1);
                }
            }

            // p = ex2(qk) * eb * mask  (eb fp16)
            #pragma unroll
            for (int j = 0; j < 4; j++) {
                const float2 e0 = __half22float2(__ldg((const __half2*)(tbr0 + n0 + 8*j + 2*gc)));
                const float2 e1 = __half22float2(__ldg((const __half2*)(tbr1 + n0 + 8*j + 2*gc)));
                const float2 mk = *(const float2*)(msm + n0 + 8*j + 2*gc);
                c[j][0] = ex2(c[j][0]) * (e0.x*mk.x);
                c[j][1] = ex2(c[j][1]) * (e0.y*mk.y);
                c[j][2] = ex2(c[j][2]) * (e1.x*mk.x);
                c[j][3] = ex2(c[j][3]) * (e1.y*mk.y);
            }

            // AV (+ row-sum tile j=4): A-frag = QK C-frag
            #pragma unroll
            for (int ks = 0; ks < 2; ks++) {
                const uint32_t a0 = pkh2(c[2*ks  ][0], c[2*ks  ][1]);
                const uint32_t a1 = pkh2(c[2*ks  ][2], c[2*ks  ][3]);
                const uint32_t a2 = pkh2(c[2*ks+1][0], c[2*ks+1][1]);
                const uint32_t a3 = pkh2(c[2*ks+1][2], c[2*ks+1][3]);
                const int kk = (n0 + 16*ks) >> 1;
                #pragma unroll
                for (int j = 0; j < 4; j++) {
                    const uint32_t* vr = vt32 + (8*j + gr)*(VSTH/2) + kk;
                    mma_f16(o[j], a0, a1, a2, a3, vr[gc], vr[gc + 4]);
                }
                const uint32_t* vr4 = vt32 + (32 + gr)*(VSTH/2) + kk;
                mma_f16(o4, a0, a1, a2, a3, vr4[gc], vr4[gc + 4]);
            }
        }

        // row sums live in col 0 of the j=4 tile (gc==0 lanes)
        const float s0 = __shfl_sync(0xffffffffu, o4[0], lane & ~3);
        const float s1 = __shfl_sync(0xffffffffu, o4[2], lane & ~3);
        const float inv0 = 1.0f / s0, inv1 = 1.0f / s1;

        #pragma unroll
        for (int j = 0; j < 4; j++) {
            const int col = h*DH + 8*j + 2*gc;
            const size_t r0 = (size_t)(i*NSEQ + jq0 + gr)*CIN + col;
            const size_t r1 = (size_t)(i*NSEQ + jq0 + gr + 8)*CIN + col;
            const float2 g0 = __half22float2(*(const __half2*)(g_acth + r0));
            const float2 g1 = __half22float2(*(const __half2*)(g_acth + r1));
            *(__half2*)(g_acth + r0) =
                __floats2half2_rn(o[j][0]*inv0*g0.x, o[j][1]*inv0*g0.y);
            *(__half2*)(g_acth + r1) =
                __floats2half2_rn(o[j][2]*inv1*g1.x, o[j][3]*inv1*g1.y);
        }
    }
}

// ============================================================================
// Kernel 3: out = act @ wo^T + bo  (fp16 mma; act staged via raw cp.async)
// ============================================================================
__global__ __launch_bounds__(256, 2) void k3_out(
    const float* __restrict__ bo, float* __restrict__ out)
{
    extern __shared__ char smc[];
    char* wb[2] = { smc, smc + 64*WSB };

    const int tid  = threadIdx.x;
    const int warp = tid >> 5, lane = tid & 31;
    const int gr   = lane >> 2, gc = lane & 3;
    const int t0   = blockIdx.x * 128;

    const uint32_t xsu = s2u(smc);
    #pragma unroll
    for (int s = 0; s < 8; s++) {
        const int idx = tid + 256*s;
        const int lt = idx >> 4, ch = idx & 15;
        cpa16(xsu + lt*XSB + ch*16, g_acth + (size_t)(t0+lt)*CIN + ch*8);
    }
    CPA_COMMIT();
    CPA_WAIT(0);
    __syncthreads();

    const int m0 = warp * 16;
    uint32_t a[8][4];
    #pragma unroll
    for (int ks = 0; ks < 8; ks++) {
        const char* rp = smc + (m0+gr)*XSB + ks*32 + gc*4;
        a[ks][0] = *(const uint32_t*)(rp);
        a[ks][1] = *(const uint32_t*)(rp + 8*XSB);
        a[ks][2] = *(const uint32_t*)(rp + 16);
        a[ks][3] = *(const uint32_t*)(rp + 8*XSB + 16);
    }
    __syncthreads();

    const uint32_t wbu[2] = { s2u(wb[0]), s2u(wb[1]) };
    #pragma unroll
    for (int q = 0; q < 2; q++) {
        const __half* src = g_wh + 4*16384 + q*8192;
        #pragma unroll
        for (int s = 0; s < 4; s++) {
            const int idx = tid + 256*s;
            const int o = idx >> 4, ch = idx & 15;
            cpa16(wbu[q] + o*WSB + ch*16, src + o*128 + ch*8);
        }
        CPA_COMMIT();
    }

    const int tok = t0 + m0 + gr;
    for (int hf = 0; hf < 2; hf++) {
        if (hf == 0) { CPA_WAIT(1); } else { CPA_WAIT(0); }
        __syncthreads();

        const char* wS = wb[hf];
        float acc[8][4];
        #pragma unroll
        for (int nt = 0; nt < 8; nt++)
            #pragma unroll
            for (int e = 0; e < 4; e++) acc[nt][e] = 0.f;

        #pragma unroll
        for (int ks = 0; ks < 8; ks++) {
            #pragma unroll
            for (int nt = 0; nt < 8; nt++) {
                const uint2 b = *(const uint2*)(wS + (nt*8+gr)*WSB + ks*32 + gc*8);
                mma_f16(acc[nt], a[ks][0], a[ks][1], a[ks][2], a[ks][3], b.x, b.y);
            }
        }

        #pragma unroll
        for (int nt = 0; nt < 8; nt++) {
            const int o = hf*64 + nt*8 + 2*gc;
            const float2 bov = __ldg((const float2*)(bo + o));
            *(float2*)(out + (size_t)tok*CIN + o) =
                make_float2(acc[nt][0]+bov.x, acc[nt][1]+bov.y);
            *(float2*)(out + (size_t)(tok+8)*CIN + o) =
                make_float2(acc[nt][2]+bov.x, acc[nt][3]+bov.y);
        }
    }
}

// ============================================================================
extern "C" void kernel_launch(void* const* d_in, const int* in_sizes, int n_in,
                              void* d_out, int out_size)
{
    const float* x     = (const float*)d_in[0];
    const float* mask  = (const float*)d_in[1];
    const float* gamma = (const float*)d_in[2];
    const float* beta  = (const float*)d_in[3];
    const float* wbias = (const float*)d_in[4];
    const float* wq    = (const float*)d_in[5];
    const float* wk    = (const float*)d_in[6];
    const float* wv    = (const float*)d_in[7];
    const float* wg    = (const float*)d_in[8];
    const float* bg    = (const float*)d_in[9];
    const float* wo    = (const float*)d_in[10];
    const float* bo    = (const float*)d_in[11];
    float* out = (float*)d_out;

    const int smem_gemm = 2 * 64 * WSB;           // 36,864 B

    cudaFuncSetAttribute(k1_ln_proj, cudaFuncAttributeMaxDynamicSharedMemorySize, smem_gemm);
    cudaFuncSetAttribute(k2_attn,   cudaFuncAttributeMaxDynamicSharedMemorySize, K2_SMEM);
    cudaFuncSetAttribute(k3_out,    cudaFuncAttributeMaxDynamicSharedMemorySize, smem_gemm);

    k0_prep  <<<320, 256>>>(wq, wk, wv, wg, wo, wbias);
    k1_ln_proj<<<NTOK/128, 256, smem_gemm>>>(x, gamma, beta, bg);
    k2_attn  <<<NSEQ*NH,  384, K2_SMEM>>>(mask);
    k3_out   <<<NTOK/128, 256, smem_gemm>>>(bo, out);
}